// round 15
// baseline (speedup 1.0000x reference)
#include <cuda_runtime.h>
#include <cuda_fp16.h>
#include <cstdint>

#define NN 100000
#define EE 3200000
#define H 128

// ---------------- scratch (__device__ globals; allocation-free rule) ----------------
__device__ float  g_X[(size_t)NN * H];    // 51.2 MB fp32 ping
__device__ float  g_A[(size_t)NN * H];    // 51.2 MB fp32 pong
__device__ __half g_Xh[(size_t)NN * H];   // 25.6 MB fp16 conv-GEMM out (gather source)
__device__ float  g_dinv[NN];
__device__ int    g_deg[100352];          // padded for int4 zeroing
__device__ int    g_off[NN + 1];
__device__ int    g_cur[100352];
__device__ int    g_csrc[EE];             // CSR: src per incoming edge of dst
__device__ float  g_cnrm[EE];             // CSR: norm per incoming edge
__device__ int    g_is64;

__device__ __forceinline__ float fast_tanh(float x) {
    float t = __expf(-2.0f * fabsf(x));
    float r = __fdividef(1.0f - t, 1.0f + t);
    return copysignf(r, x);
}

// ---------------- edge dtype detection (int32 vs int64) ----------------
__global__ void detect_k(const int* __restrict__ ei32) {
    __shared__ int nz;
    if (threadIdx.x == 0) nz = 0;
    __syncthreads();
    int c = 0;
    for (int k = threadIdx.x; k < 4096; k += blockDim.x)
        if (ei32[2 * k + 1] != 0) c++;
    atomicAdd(&nz, c);
    __syncthreads();
    if (threadIdx.x == 0) g_is64 = (nz == 0) ? 1 : 0;
}

__device__ __forceinline__ int edge_val(const void* ei, long long E, long long idx, int row) {
    if (g_is64) return (int)((const long long*)ei)[row ? E + idx : idx];
    return ((const int*)ei)[row ? E + idx : idx];
}

// ---------------- zero ints ----------------
__global__ void zeroi_k(int4* __restrict__ p, int n4) {
    int i = blockIdx.x * blockDim.x + threadIdx.x;
    if (i < n4) p[i] = make_int4(0, 0, 0, 0);
}

// ---------------- degree count ----------------
__global__ void deg_k(const void* __restrict__ ei, long long E, int* __restrict__ deg) {
    long long e = (long long)blockIdx.x * blockDim.x + threadIdx.x;
    if (e < E) atomicAdd(&deg[edge_val(ei, E, e, 1)], 1);
}

__global__ void dinv_k(const int* __restrict__ deg, float* __restrict__ dinv, int n) {
    int i = blockIdx.x * blockDim.x + threadIdx.x;
    if (i < n) dinv[i] = rsqrtf((float)deg[i] + 2.0f);   // improved self-loop: +2
}

// ---------------- single-block scan: deg -> off, cur ----------------
__global__ void __launch_bounds__(1024) scan_k(const int* __restrict__ deg,
                                               int* __restrict__ off,
                                               int* __restrict__ cur, int n) {
    __shared__ int part[1024];
    int t = threadIdx.x;
    int chunk = (n + 1023) / 1024;
    int lo = t * chunk, hi = lo + chunk < n ? lo + chunk : n;
    int s = 0;
    for (int i = lo; i < hi; i++) s += deg[i];
    part[t] = s;
    __syncthreads();
    for (int o = 1; o < 1024; o <<= 1) {
        int v = (t >= o) ? part[t - o] : 0;
        __syncthreads();
        part[t] += v;
        __syncthreads();
    }
    int base = (t == 0) ? 0 : part[t - 1];
    for (int i = lo; i < hi; i++) {
        off[i] = base; cur[i] = base; base += deg[i];
    }
    if (t == 0) off[n] = part[1023];
}

// ---------------- CSR fill ----------------
__global__ void fill_k(const void* __restrict__ ei, long long E,
                       const float* __restrict__ dinv,
                       int* __restrict__ cur, int* __restrict__ csrc,
                       float* __restrict__ cnrm) {
    long long e = (long long)blockIdx.x * blockDim.x + threadIdx.x;
    if (e >= E) return;
    int s = edge_val(ei, E, e, 0);
    int d = edge_val(ei, E, e, 1);
    int pos = atomicAdd(&cur[d], 1);
    csrc[pos] = s;
    cnrm[pos] = dinv[s] * dinv[d];
}

// ---------------- gather (fp16 rows, 256B) + conv epilogue, 4-wide MLP ----------------
// out_fp32 = tanh(sum_edges(norm * xh[src]) + xh[node]*2dinv^2 + b)
__global__ void __launch_bounds__(256) aggregate_k(
    const __half* __restrict__ xw, const int* __restrict__ off,
    const int* __restrict__ deg, const int* __restrict__ csrc,
    const float* __restrict__ cnrm, const float* __restrict__ dinv,
    const float* __restrict__ bias, float* __restrict__ out, int n)
{
    int node = (blockIdx.x * 256 + threadIdx.x) >> 5;
    int lane = threadIdx.x & 31;
    if (node >= n) return;
    int j = off[node];
    int end = j + deg[node];
    const uint2* X2 = (const uint2*)xw;   // 8B = 4 halves per lane
    float4 acc = make_float4(0.f, 0.f, 0.f, 0.f);
    // 4-wide: 4 independent row-gathers in flight (8 x 128B lines)
    for (; j + 3 < end; j += 4) {
        int s0 = __ldg(&csrc[j]);       int s1 = __ldg(&csrc[j + 1]);
        int s2 = __ldg(&csrc[j + 2]);   int s3 = __ldg(&csrc[j + 3]);
        float n0 = __ldg(&cnrm[j]);     float n1 = __ldg(&cnrm[j + 1]);
        float n2 = __ldg(&cnrm[j + 2]); float n3 = __ldg(&cnrm[j + 3]);
        uint2 r0 = X2[(size_t)s0 * 32 + lane];
        uint2 r1 = X2[(size_t)s1 * 32 + lane];
        uint2 r2 = X2[(size_t)s2 * 32 + lane];
        uint2 r3 = X2[(size_t)s3 * 32 + lane];
        float2 p01, p23;
        p01 = __half22float2(*(__half2*)&r0.x); p23 = __half22float2(*(__half2*)&r0.y);
        acc.x = fmaf(p01.x, n0, acc.x); acc.y = fmaf(p01.y, n0, acc.y);
        acc.z = fmaf(p23.x, n0, acc.z); acc.w = fmaf(p23.y, n0, acc.w);
        p01 = __half22float2(*(__half2*)&r1.x); p23 = __half22float2(*(__half2*)&r1.y);
        acc.x = fmaf(p01.x, n1, acc.x); acc.y = fmaf(p01.y, n1, acc.y);
        acc.z = fmaf(p23.x, n1, acc.z); acc.w = fmaf(p23.y, n1, acc.w);
        p01 = __half22float2(*(__half2*)&r2.x); p23 = __half22float2(*(__half2*)&r2.y);
        acc.x = fmaf(p01.x, n2, acc.x); acc.y = fmaf(p01.y, n2, acc.y);
        acc.z = fmaf(p23.x, n2, acc.z); acc.w = fmaf(p23.y, n2, acc.w);
        p01 = __half22float2(*(__half2*)&r3.x); p23 = __half22float2(*(__half2*)&r3.y);
        acc.x = fmaf(p01.x, n3, acc.x); acc.y = fmaf(p01.y, n3, acc.y);
        acc.z = fmaf(p23.x, n3, acc.z); acc.w = fmaf(p23.y, n3, acc.w);
    }
    for (; j < end; j++) {
        int s0 = __ldg(&csrc[j]);
        float n0 = __ldg(&cnrm[j]);
        uint2 r0 = X2[(size_t)s0 * 32 + lane];
        float2 a01 = __half22float2(*(__half2*)&r0.x);
        float2 a23 = __half22float2(*(__half2*)&r0.y);
        acc.x = fmaf(a01.x, n0, acc.x); acc.y = fmaf(a01.y, n0, acc.y);
        acc.z = fmaf(a23.x, n0, acc.z); acc.w = fmaf(a23.y, n0, acc.w);
    }
    float di = dinv[node];
    float sw = 2.0f * di * di;
    uint2 rs = X2[(size_t)node * 32 + lane];
    float2 s01 = __half22float2(*(__half2*)&rs.x);
    float2 s23 = __half22float2(*(__half2*)&rs.y);
    float4 bv = ((const float4*)bias)[lane];
    acc.x = fast_tanh(fmaf(s01.x, sw, acc.x) + bv.x);
    acc.y = fast_tanh(fmaf(s01.y, sw, acc.y) + bv.y);
    acc.z = fast_tanh(fmaf(s23.x, sw, acc.z) + bv.z);
    acc.w = fast_tanh(fmaf(s23.y, sw, acc.w) + bv.w);
    ((float4*)out)[(size_t)node * 32 + lane] = acc;
}

// ---------------- tf32 MMA common ----------------
#define ASTRIDE 132
#define WSTRIDE 136
// CTA tile 64 rows x 128 cols: A 64*132*4 + W 128*136*4 = 103424 B -> 2 CTAs/SM
#define TC_SMEM ((64 * ASTRIDE + 128 * WSTRIDE) * 4)
#define HSTRIDE 136    // halves per row in fp16 staging buffer: 272B = 16B-aligned rows

__device__ __forceinline__ float to_tf32(float x) {
    uint32_t u;
    asm("cvt.rna.tf32.f32 %0, %1;" : "=r"(u) : "f"(x));
    return __uint_as_float(u);
}

__device__ __forceinline__ void mma_tf32(float* c, const uint32_t* a,
                                         uint32_t b0, uint32_t b1) {
    asm volatile(
        "mma.sync.aligned.m16n8k8.row.col.f32.tf32.tf32.f32 "
        "{%0,%1,%2,%3}, {%4,%5,%6,%7}, {%8,%9}, {%0,%1,%2,%3};"
        : "+f"(c[0]), "+f"(c[1]), "+f"(c[2]), "+f"(c[3])
        : "r"(a[0]), "r"(a[1]), "r"(a[2]), "r"(a[3]), "r"(b0), "r"(b1));
}

// mainloop over one 32-row x 32-col warp tile (K=128)
__device__ __forceinline__ void mma_tile_128(
    const float* __restrict__ Asrc, const float* __restrict__ Wn,
    int strip, int nquart, int gid, int tg, float acc[2][4][4])
{
    #pragma unroll
    for (int r = 0; r < 2; r++)
        #pragma unroll
        for (int j = 0; j < 4; j++)
            #pragma unroll
            for (int q = 0; q < 4; q++) acc[r][j][q] = 0.f;

    const float* A0 = Asrc + (strip + gid) * ASTRIDE + tg;
    const float* B0 = Wn + tg * WSTRIDE + nquart + gid;

    #pragma unroll 4
    for (int ks = 0; ks < 16; ks++) {
        int k0 = ks * 8;
        uint32_t a[2][4];
        #pragma unroll
        for (int r = 0; r < 2; r++) {
            const float* p = A0 + r * 16 * ASTRIDE + k0;
            a[r][0] = __float_as_uint(p[0]);
            a[r][1] = __float_as_uint(p[8 * ASTRIDE]);
            a[r][2] = __float_as_uint(p[4]);
            a[r][3] = __float_as_uint(p[8 * ASTRIDE + 4]);
        }
        const float* q = B0 + k0 * WSTRIDE;
        #pragma unroll
        for (int j = 0; j < 4; j++) {
            uint32_t b0 = __float_as_uint(q[j * 8]);
            uint32_t b1 = __float_as_uint(q[4 * WSTRIDE + j * 8]);
            mma_tf32(acc[0][j], a[0], b0, b1);
            mma_tf32(acc[1][j], a[1], b0, b1);
        }
    }
}

// ---------------- GEMM [n,128]@[128,128]: CTA 64 rows, 256 thr ------------
// OUTH=1: fp16 output staged via smem for coalesced STG.128.
template <bool TANH, bool BIAS, bool OUTH>
__global__ void __launch_bounds__(256) gemm_tc(
    const float* __restrict__ in, const float* __restrict__ W,
    const float* __restrict__ bias, float* __restrict__ outf,
    __half* __restrict__ outh, int n)
{
    extern __shared__ float sm[];
    float* Asm = sm;                     // [64 rows][k] stride ASTRIDE
    float* Wn  = sm + 64 * ASTRIDE;      // [k][c] stride WSTRIDE

    int tid = threadIdx.x, lane = tid & 31, w = tid >> 5;
    int nb = blockIdx.x * 64;

    // stage A: 64 rows (tf32-rounded)
    const float4* In4 = (const float4*)in;
    #pragma unroll
    for (int i = tid; i < 2048; i += 256) {
        int row = i >> 5, q = i & 31;
        int node = nb + row < n ? nb + row : n - 1;
        float4 v = In4[(size_t)node * 32 + q];
        v.x = to_tf32(v.x); v.y = to_tf32(v.y);
        v.z = to_tf32(v.z); v.w = to_tf32(v.w);
        *(float4*)(Asm + row * ASTRIDE + q * 4) = v;
    }
    // stage W natural [k][c] (tf32-rounded)
    const float4* W4 = (const float4*)W;
    #pragma unroll
    for (int i = tid; i < 4096; i += 256) {
        int k = i >> 5, q = i & 31;
        float4 v = W4[k * 32 + q];
        v.x = to_tf32(v.x); v.y = to_tf32(v.y);
        v.z = to_tf32(v.z); v.w = to_tf32(v.w);
        *(float4*)(Wn + k * WSTRIDE + q * 4) = v;
    }
    __syncthreads();

    int strip  = (w >> 2) * 32;    // 0 or 32
    int nquart = (w & 3) * 32;     // 0,32,64,96
    int gid = lane >> 2, tg = lane & 3;

    float acc[2][4][4];
    mma_tile_128(Asm, Wn, strip, nquart, gid, tg, acc);

    if (OUTH) {
        // stage fp16 tile in smem (reuse Asm region), then coalesced STG.128
        __syncthreads();                  // everyone done reading Asm
        __half* Hs = (__half*)Asm;        // [64][HSTRIDE] halves, 272B rows
        #pragma unroll
        for (int j = 0; j < 4; j++) {
            int col = nquart + 8 * j + 2 * tg;
            #pragma unroll
            for (int r = 0; r < 2; r++) {
                int row0 = strip + r * 16 + gid;
                *(__half2*)(Hs + row0 * HSTRIDE + col) =
                    __floats2half2_rn(acc[r][j][0], acc[r][j][1]);
                *(__half2*)(Hs + (row0 + 8) * HSTRIDE + col) =
                    __floats2half2_rn(acc[r][j][2], acc[r][j][3]);
            }
        }
        __syncthreads();
        // 64 rows x 128 halves: 16B chunks, 1024 chunks total, 4 iters
        #pragma unroll
        for (int i = tid; i < 1024; i += 256) {
            int row = i >> 4, c8 = (i & 15) * 8;
            uint4 v = *(uint4*)(Hs + row * HSTRIDE + c8);
            int node = nb + row;
            if (node < n) *(uint4*)(outh + (size_t)node * 128 + c8) = v;
        }
    } else {
        #pragma unroll
        for (int j = 0; j < 4; j++) {
            int col = nquart + 8 * j + 2 * tg;
            float2 bv = BIAS ? __ldg((const float2*)(bias + col)) : make_float2(0.f, 0.f);
            #pragma unroll
            for (int r = 0; r < 2; r++) {
                int row0 = nb + strip + r * 16 + gid;
                int row1 = row0 + 8;
                float v0 = acc[r][j][0] + bv.x;
                float v1 = acc[r][j][1] + bv.y;
                float v2 = acc[r][j][2] + bv.x;
                float v3 = acc[r][j][3] + bv.y;
                if (TANH) {
                    v0 = fast_tanh(v0); v1 = fast_tanh(v1);
                    v2 = fast_tanh(v2); v3 = fast_tanh(v3);
                }
                if (row0 < n) *(float2*)(outf + (size_t)row0 * 128 + col) = make_float2(v0, v1);
                if (row1 < n) *(float2*)(outf + (size_t)row1 * 128 + col) = make_float2(v2, v3);
            }
        }
    }
}

// ---------------- final 128 -> 3 ----------------
__global__ void __launch_bounds__(256) out_k(
    const float* __restrict__ h, const float* __restrict__ lw4,
    const float* __restrict__ lb4, float* __restrict__ out, int n)
{
    int wid = (blockIdx.x * 256 + threadIdx.x) >> 5;
    int lane = threadIdx.x & 31;
    if (wid >= n) return;
    const float* row = h + (size_t)wid * 128;
    float a0 = 0.f, a1 = 0.f, a2 = 0.f;
    #pragma unroll
    for (int k = lane; k < 128; k += 32) {
        float hv = row[k];
        a0 = fmaf(hv, __ldg(&lw4[k * 3 + 0]), a0);
        a1 = fmaf(hv, __ldg(&lw4[k * 3 + 1]), a1);
        a2 = fmaf(hv, __ldg(&lw4[k * 3 + 2]), a2);
    }
    #pragma unroll
    for (int o = 16; o; o >>= 1) {
        a0 += __shfl_down_sync(0xffffffffu, a0, o);
        a1 += __shfl_down_sync(0xffffffffu, a1, o);
        a2 += __shfl_down_sync(0xffffffffu, a2, o);
    }
    if (lane == 0) {
        out[(size_t)wid * 3 + 0] = a0 + lb4[0];
        out[(size_t)wid * 3 + 1] = a1 + lb4[1];
        out[(size_t)wid * 3 + 2] = a2 + lb4[2];
    }
}

// ---------------- launch ----------------
extern "C" void kernel_launch(void* const* d_in, const int* in_sizes, int n_in,
                              void* d_out, int out_size)
{
    const float* x   = (const float*)d_in[0];
    const void*  ei  = d_in[1];
    const float* W1  = (const float*)d_in[2];
    const float* b1  = (const float*)d_in[3];
    const float* W2  = (const float*)d_in[4];
    const float* b2  = (const float*)d_in[5];
    const float* lw1 = (const float*)d_in[6];
    const float* lb1 = (const float*)d_in[7];
    const float* lw2 = (const float*)d_in[8];
    const float* lb2 = (const float*)d_in[9];
    const float* lw3 = (const float*)d_in[10];
    const float* lb3 = (const float*)d_in[11];
    const float* lw4 = (const float*)d_in[12];
    const float* lb4 = (const float*)d_in[13];
    float* out = (float*)d_out;

    int n = in_sizes[0] / H;
    long long E = (long long)in_sizes[1] / 2;

    float *pX, *pA, *pD, *pNrm;
    __half* pXh;
    int *pDeg, *pOff, *pCur, *pSrc;
    cudaGetSymbolAddress((void**)&pX, g_X);
    cudaGetSymbolAddress((void**)&pA, g_A);
    cudaGetSymbolAddress((void**)&pXh, g_Xh);
    cudaGetSymbolAddress((void**)&pD, g_dinv);
    cudaGetSymbolAddress((void**)&pDeg, g_deg);
    cudaGetSymbolAddress((void**)&pOff, g_off);
    cudaGetSymbolAddress((void**)&pCur, g_cur);
    cudaGetSymbolAddress((void**)&pSrc, g_csrc);
    cudaGetSymbolAddress((void**)&pNrm, g_cnrm);

    cudaFuncSetAttribute((const void*)gemm_tc<false, false, true>,
                         cudaFuncAttributeMaxDynamicSharedMemorySize, TC_SMEM);
    cudaFuncSetAttribute((const void*)gemm_tc<true, true, false>,
                         cudaFuncAttributeMaxDynamicSharedMemorySize, TC_SMEM);

    int gb  = (n + 63) / 64;               // gemm blocks (64-row tiles)
    int nwb = (n + 7) / 8;                 // warp-per-node blocks
    int eb  = (int)((E + 255) / 256);      // thread-per-edge blocks

    // Launch order keeps the conv1 GEMM at index 3 so ncu (-s 5 -c 1) profiles it.
    detect_k<<<1, 256>>>((const int*)ei);                                  // 0
    zeroi_k<<<(100352 / 4 + 255) / 256, 256>>>((int4*)pDeg, 100352 / 4);   // 1
    deg_k<<<eb, 256>>>(ei, E, pDeg);                                       // 2
    gemm_tc<false, false, true><<<gb, 256, TC_SMEM>>>(x, W1, nullptr, nullptr, pXh, n); // 3
    dinv_k<<<(n + 255) / 256, 256>>>(pDeg, pD, n);                         // 4
    scan_k<<<1, 1024>>>(pDeg, pOff, pCur, n);                              // 5
    fill_k<<<eb, 256>>>(ei, E, pD, pCur, pSrc, pNrm);                      // 6

    // conv1 aggregate: A = tanh(gather_fp16(Xh) + self + b1)  (fp32 out)
    aggregate_k<<<nwb, 256>>>(pXh, pOff, pDeg, pSrc, pNrm, pD, b1, pA, n);

    // conv2: Xh = A @ W2 (fp16 out); X = tanh(gather(Xh) + self + b2)
    gemm_tc<false, false, true><<<gb, 256, TC_SMEM>>>(pA, W2, nullptr, nullptr, pXh, n);
    aggregate_k<<<nwb, 256>>>(pXh, pOff, pDeg, pSrc, pNrm, pD, b2, pX, n);

    // MLP head (fp32, r12 structure)
    gemm_tc<true, true, false><<<gb, 256, TC_SMEM>>>(pX, lw1, lb1, pA, nullptr, n);
    gemm_tc<true, true, false><<<gb, 256, TC_SMEM>>>(pA, lw2, lb2, pX, nullptr, n);
    gemm_tc<true, true, false><<<gb, 256, TC_SMEM>>>(pX, lw3, lb3, pA, nullptr, n);
    out_k<<<(n + 7) / 8, 256>>>(pA, lw4, lb4, out, n);
}

// round 16
// speedup vs baseline: 1.0414x; 1.0414x over previous
#include <cuda_runtime.h>
#include <cuda_fp16.h>
#include <cstdint>

#define NN 100000
#define EE 3200000
#define H 128

// ---------------- scratch (__device__ globals; allocation-free rule) ----------------
__device__ __half g_Xh[(size_t)NN * H];   // 25.6 MB fp16 ping
__device__ __half g_Ah[(size_t)NN * H];   // 25.6 MB fp16 pong
__device__ float  g_dinv[NN];
__device__ int    g_deg[100352];          // padded for int4 zeroing
__device__ int    g_off[NN + 1];
__device__ int    g_cur[100352];
__device__ int    g_csrc[EE];             // CSR: src per incoming edge of dst
__device__ float  g_cnrm[EE];             // CSR: norm per incoming edge
__device__ int    g_is64;

__device__ __forceinline__ float fast_tanh(float x) {
    float t = __expf(-2.0f * fabsf(x));
    float r = __fdividef(1.0f - t, 1.0f + t);
    return copysignf(r, x);
}

// ---------------- edge dtype detection (int32 vs int64) ----------------
__global__ void detect_k(const int* __restrict__ ei32) {
    __shared__ int nz;
    if (threadIdx.x == 0) nz = 0;
    __syncthreads();
    int c = 0;
    for (int k = threadIdx.x; k < 4096; k += blockDim.x)
        if (ei32[2 * k + 1] != 0) c++;
    atomicAdd(&nz, c);
    __syncthreads();
    if (threadIdx.x == 0) g_is64 = (nz == 0) ? 1 : 0;
}

__device__ __forceinline__ int edge_val(const void* ei, long long E, long long idx, int row) {
    if (g_is64) return (int)((const long long*)ei)[row ? E + idx : idx];
    return ((const int*)ei)[row ? E + idx : idx];
}

// ---------------- zero ints ----------------
__global__ void zeroi_k(int4* __restrict__ p, int n4) {
    int i = blockIdx.x * blockDim.x + threadIdx.x;
    if (i < n4) p[i] = make_int4(0, 0, 0, 0);
}

// ---------------- degree count ----------------
__global__ void deg_k(const void* __restrict__ ei, long long E, int* __restrict__ deg) {
    long long e = (long long)blockIdx.x * blockDim.x + threadIdx.x;
    if (e < E) atomicAdd(&deg[edge_val(ei, E, e, 1)], 1);
}

__global__ void dinv_k(const int* __restrict__ deg, float* __restrict__ dinv, int n) {
    int i = blockIdx.x * blockDim.x + threadIdx.x;
    if (i < n) dinv[i] = rsqrtf((float)deg[i] + 2.0f);   // improved self-loop: +2
}

// ---------------- single-block scan: deg -> off, cur ----------------
__global__ void __launch_bounds__(1024) scan_k(const int* __restrict__ deg,
                                               int* __restrict__ off,
                                               int* __restrict__ cur, int n) {
    __shared__ int part[1024];
    int t = threadIdx.x;
    int chunk = (n + 1023) / 1024;
    int lo = t * chunk, hi = lo + chunk < n ? lo + chunk : n;
    int s = 0;
    for (int i = lo; i < hi; i++) s += deg[i];
    part[t] = s;
    __syncthreads();
    for (int o = 1; o < 1024; o <<= 1) {
        int v = (t >= o) ? part[t - o] : 0;
        __syncthreads();
        part[t] += v;
        __syncthreads();
    }
    int base = (t == 0) ? 0 : part[t - 1];
    for (int i = lo; i < hi; i++) {
        off[i] = base; cur[i] = base; base += deg[i];
    }
    if (t == 0) off[n] = part[1023];
}

// ---------------- CSR fill ----------------
__global__ void fill_k(const void* __restrict__ ei, long long E,
                       const float* __restrict__ dinv,
                       int* __restrict__ cur, int* __restrict__ csrc,
                       float* __restrict__ cnrm) {
    long long e = (long long)blockIdx.x * blockDim.x + threadIdx.x;
    if (e >= E) return;
    int s = edge_val(ei, E, e, 0);
    int d = edge_val(ei, E, e, 1);
    int pos = atomicAdd(&cur[d], 1);
    csrc[pos] = s;
    cnrm[pos] = dinv[s] * dinv[d];
}

// ---------------- gather (fp16 rows, 256B), 2-wide, fp16 out ----------------
// out_fp16 = tanh(sum_edges(norm * xh[src]) + xh[node]*2dinv^2 + b)
__global__ void __launch_bounds__(256) aggregate_k(
    const __half* __restrict__ xw, const int* __restrict__ off,
    const int* __restrict__ deg, const int* __restrict__ csrc,
    const float* __restrict__ cnrm, const float* __restrict__ dinv,
    const float* __restrict__ bias, __half* __restrict__ out, int n)
{
    int node = (blockIdx.x * 256 + threadIdx.x) >> 5;
    int lane = threadIdx.x & 31;
    if (node >= n) return;
    int j = off[node];
    int end = j + deg[node];
    const uint2* X2 = (const uint2*)xw;   // 8B = 4 halves per lane
    float4 acc = make_float4(0.f, 0.f, 0.f, 0.f);
    for (; j + 1 < end; j += 2) {
        int s0 = __ldg(&csrc[j]);     int s1 = __ldg(&csrc[j + 1]);
        float n0 = __ldg(&cnrm[j]);   float n1 = __ldg(&cnrm[j + 1]);
        uint2 r0 = X2[(size_t)s0 * 32 + lane];
        uint2 r1 = X2[(size_t)s1 * 32 + lane];
        float2 a01 = __half22float2(*(__half2*)&r0.x);
        float2 a23 = __half22float2(*(__half2*)&r0.y);
        float2 b01 = __half22float2(*(__half2*)&r1.x);
        float2 b23 = __half22float2(*(__half2*)&r1.y);
        acc.x = fmaf(a01.x, n0, acc.x); acc.y = fmaf(a01.y, n0, acc.y);
        acc.z = fmaf(a23.x, n0, acc.z); acc.w = fmaf(a23.y, n0, acc.w);
        acc.x = fmaf(b01.x, n1, acc.x); acc.y = fmaf(b01.y, n1, acc.y);
        acc.z = fmaf(b23.x, n1, acc.z); acc.w = fmaf(b23.y, n1, acc.w);
    }
    if (j < end) {
        int s0 = __ldg(&csrc[j]);
        float n0 = __ldg(&cnrm[j]);
        uint2 r0 = X2[(size_t)s0 * 32 + lane];
        float2 a01 = __half22float2(*(__half2*)&r0.x);
        float2 a23 = __half22float2(*(__half2*)&r0.y);
        acc.x = fmaf(a01.x, n0, acc.x); acc.y = fmaf(a01.y, n0, acc.y);
        acc.z = fmaf(a23.x, n0, acc.z); acc.w = fmaf(a23.y, n0, acc.w);
    }
    float di = dinv[node];
    float sw = 2.0f * di * di;
    uint2 rs = X2[(size_t)node * 32 + lane];
    float2 s01 = __half22float2(*(__half2*)&rs.x);
    float2 s23 = __half22float2(*(__half2*)&rs.y);
    float4 bv = ((const float4*)bias)[lane];
    acc.x = fast_tanh(fmaf(s01.x, sw, acc.x) + bv.x);
    acc.y = fast_tanh(fmaf(s01.y, sw, acc.y) + bv.y);
    acc.z = fast_tanh(fmaf(s23.x, sw, acc.z) + bv.z);
    acc.w = fast_tanh(fmaf(s23.y, sw, acc.w) + bv.w);
    uint2 pk;
    *(__half2*)&pk.x = __floats2half2_rn(acc.x, acc.y);
    *(__half2*)&pk.y = __floats2half2_rn(acc.z, acc.w);
    ((uint2*)out)[(size_t)node * 32 + lane] = pk;
}

// ---------------- tf32 MMA common ----------------
#define ASTRIDE 132
#define WSTRIDE 136
// CTA tile 64 rows x 128 cols: A 64*132*4 + W 128*136*4 = 103424 B -> 2 CTAs/SM
#define TC_SMEM ((64 * ASTRIDE + 128 * WSTRIDE) * 4)
#define HSTRIDE 136    // halves per row in fp16 staging buffer: 272B rows, 16B-aligned

__device__ __forceinline__ float to_tf32(float x) {
    uint32_t u;
    asm("cvt.rna.tf32.f32 %0, %1;" : "=r"(u) : "f"(x));
    return __uint_as_float(u);
}

__device__ __forceinline__ void mma_tf32(float* c, const uint32_t* a,
                                         uint32_t b0, uint32_t b1) {
    asm volatile(
        "mma.sync.aligned.m16n8k8.row.col.f32.tf32.tf32.f32 "
        "{%0,%1,%2,%3}, {%4,%5,%6,%7}, {%8,%9}, {%0,%1,%2,%3};"
        : "+f"(c[0]), "+f"(c[1]), "+f"(c[2]), "+f"(c[3])
        : "r"(a[0]), "r"(a[1]), "r"(a[2]), "r"(a[3]), "r"(b0), "r"(b1));
}

// mainloop over one 32-row x 32-col warp tile (K=128)
__device__ __forceinline__ void mma_tile_128(
    const float* __restrict__ Asrc, const float* __restrict__ Wn,
    int strip, int nquart, int gid, int tg, float acc[2][4][4])
{
    #pragma unroll
    for (int r = 0; r < 2; r++)
        #pragma unroll
        for (int j = 0; j < 4; j++)
            #pragma unroll
            for (int q = 0; q < 4; q++) acc[r][j][q] = 0.f;

    const float* A0 = Asrc + (strip + gid) * ASTRIDE + tg;
    const float* B0 = Wn + tg * WSTRIDE + nquart + gid;

    #pragma unroll 4
    for (int ks = 0; ks < 16; ks++) {
        int k0 = ks * 8;
        uint32_t a[2][4];
        #pragma unroll
        for (int r = 0; r < 2; r++) {
            const float* p = A0 + r * 16 * ASTRIDE + k0;
            a[r][0] = __float_as_uint(p[0]);
            a[r][1] = __float_as_uint(p[8 * ASTRIDE]);
            a[r][2] = __float_as_uint(p[4]);
            a[r][3] = __float_as_uint(p[8 * ASTRIDE + 4]);
        }
        const float* q = B0 + k0 * WSTRIDE;
        #pragma unroll
        for (int j = 0; j < 4; j++) {
            uint32_t b0 = __float_as_uint(q[j * 8]);
            uint32_t b1 = __float_as_uint(q[4 * WSTRIDE + j * 8]);
            mma_tf32(acc[0][j], a[0], b0, b1);
            mma_tf32(acc[1][j], a[1], b0, b1);
        }
    }
}

// ---------------- GEMM [n,128]@[128,128]: CTA 64 rows, 256 thr, fp16 out ------------
// INH: fp16 input (fp16 values are tf32-exact, no rounding needed).
template <bool INH, bool TANH, bool BIAS>
__global__ void __launch_bounds__(256) gemm_tc(
    const float* __restrict__ inf, const __half* __restrict__ inh,
    const float* __restrict__ W, const float* __restrict__ bias,
    __half* __restrict__ outh, int n)
{
    extern __shared__ float sm[];
    float* Asm = sm;                     // [64 rows][k] stride ASTRIDE
    float* Wn  = sm + 64 * ASTRIDE;      // [k][c] stride WSTRIDE

    int tid = threadIdx.x, lane = tid & 31, w = tid >> 5;
    int nb = blockIdx.x * 64;

    // stage A: 64 rows
    if (INH) {
        const uint2* In2 = (const uint2*)inh;
        #pragma unroll
        for (int i = tid; i < 2048; i += 256) {
            int row = i >> 5, q = i & 31;
            int node = nb + row < n ? nb + row : n - 1;
            uint2 v = In2[(size_t)node * 32 + q];
            float2 p01 = __half22float2(*(__half2*)&v.x);
            float2 p23 = __half22float2(*(__half2*)&v.y);
            *(float4*)(Asm + row * ASTRIDE + q * 4) =
                make_float4(p01.x, p01.y, p23.x, p23.y);
        }
    } else {
        const float4* In4 = (const float4*)inf;
        #pragma unroll
        for (int i = tid; i < 2048; i += 256) {
            int row = i >> 5, q = i & 31;
            int node = nb + row < n ? nb + row : n - 1;
            float4 v = In4[(size_t)node * 32 + q];
            v.x = to_tf32(v.x); v.y = to_tf32(v.y);
            v.z = to_tf32(v.z); v.w = to_tf32(v.w);
            *(float4*)(Asm + row * ASTRIDE + q * 4) = v;
        }
    }
    // stage W natural [k][c] (tf32-rounded)
    const float4* W4 = (const float4*)W;
    #pragma unroll
    for (int i = tid; i < 4096; i += 256) {
        int k = i >> 5, q = i & 31;
        float4 v = W4[k * 32 + q];
        v.x = to_tf32(v.x); v.y = to_tf32(v.y);
        v.z = to_tf32(v.z); v.w = to_tf32(v.w);
        *(float4*)(Wn + k * WSTRIDE + q * 4) = v;
    }
    __syncthreads();

    int strip  = (w >> 2) * 32;    // 0 or 32
    int nquart = (w & 3) * 32;     // 0,32,64,96
    int gid = lane >> 2, tg = lane & 3;

    float acc[2][4][4];
    mma_tile_128(Asm, Wn, strip, nquart, gid, tg, acc);

    // epilogue: bias+tanh (optional), pack fp16 into smem, coalesced STG.128
    __syncthreads();                  // everyone done reading Asm
    __half* Hs = (__half*)Asm;        // [64][HSTRIDE] halves, 272B rows
    #pragma unroll
    for (int j = 0; j < 4; j++) {
        int col = nquart + 8 * j + 2 * tg;
        float2 bv = BIAS ? __ldg((const float2*)(bias + col)) : make_float2(0.f, 0.f);
        #pragma unroll
        for (int r = 0; r < 2; r++) {
            int row0 = strip + r * 16 + gid;
            float v0 = acc[r][j][0] + bv.x;
            float v1 = acc[r][j][1] + bv.y;
            float v2 = acc[r][j][2] + bv.x;
            float v3 = acc[r][j][3] + bv.y;
            if (TANH) {
                v0 = fast_tanh(v0); v1 = fast_tanh(v1);
                v2 = fast_tanh(v2); v3 = fast_tanh(v3);
            }
            *(__half2*)(Hs + row0 * HSTRIDE + col) = __floats2half2_rn(v0, v1);
            *(__half2*)(Hs + (row0 + 8) * HSTRIDE + col) = __floats2half2_rn(v2, v3);
        }
    }
    __syncthreads();
    // 64 rows x 128 halves: 16B chunks, 1024 chunks total, 4 iters
    #pragma unroll
    for (int i = tid; i < 1024; i += 256) {
        int row = i >> 4, c8 = (i & 15) * 8;
        uint4 v = *(uint4*)(Hs + row * HSTRIDE + c8);
        int node = nb + row;
        if (node < n) *(uint4*)(outh + (size_t)node * 128 + c8) = v;
    }
}

// ---------------- final 128 -> 3 (fp16 in) ----------------
__global__ void __launch_bounds__(256) out_k(
    const __half* __restrict__ h, const float* __restrict__ lw4,
    const float* __restrict__ lb4, float* __restrict__ out, int n)
{
    int wid = (blockIdx.x * 256 + threadIdx.x) >> 5;
    int lane = threadIdx.x & 31;
    if (wid >= n) return;
    // lane owns cols lane*4..lane*4+3
    uint2 v2 = ((const uint2*)(h + (size_t)wid * 128))[lane];
    float2 c01 = __half22float2(*(__half2*)&v2.x);
    float2 c23 = __half22float2(*(__half2*)&v2.y);
    const float* wrow = lw4 + lane * 12;
    float a0 = c01.x * wrow[0] + c01.y * wrow[3] + c23.x * wrow[6] + c23.y * wrow[9];
    float a1 = c01.x * wrow[1] + c01.y * wrow[4] + c23.x * wrow[7] + c23.y * wrow[10];
    float a2 = c01.x * wrow[2] + c01.y * wrow[5] + c23.x * wrow[8] + c23.y * wrow[11];
    #pragma unroll
    for (int o = 16; o; o >>= 1) {
        a0 += __shfl_down_sync(0xffffffffu, a0, o);
        a1 += __shfl_down_sync(0xffffffffu, a1, o);
        a2 += __shfl_down_sync(0xffffffffu, a2, o);
    }
    if (lane == 0) {
        out[(size_t)wid * 3 + 0] = a0 + __ldg(&lb4[0]);
        out[(size_t)wid * 3 + 1] = a1 + __ldg(&lb4[1]);
        out[(size_t)wid * 3 + 2] = a2 + __ldg(&lb4[2]);
    }
}

// ---------------- launch ----------------
extern "C" void kernel_launch(void* const* d_in, const int* in_sizes, int n_in,
                              void* d_out, int out_size)
{
    const float* x   = (const float*)d_in[0];
    const void*  ei  = d_in[1];
    const float* W1  = (const float*)d_in[2];
    const float* b1  = (const float*)d_in[3];
    const float* W2  = (const float*)d_in[4];
    const float* b2  = (const float*)d_in[5];
    const float* lw1 = (const float*)d_in[6];
    const float* lb1 = (const float*)d_in[7];
    const float* lw2 = (const float*)d_in[8];
    const float* lb2 = (const float*)d_in[9];
    const float* lw3 = (const float*)d_in[10];
    const float* lb3 = (const float*)d_in[11];
    const float* lw4 = (const float*)d_in[12];
    const float* lb4 = (const float*)d_in[13];
    float* out = (float*)d_out;

    int n = in_sizes[0] / H;
    long long E = (long long)in_sizes[1] / 2;

    float *pD, *pNrm;
    __half *pXh, *pAh;
    int *pDeg, *pOff, *pCur, *pSrc;
    cudaGetSymbolAddress((void**)&pXh, g_Xh);
    cudaGetSymbolAddress((void**)&pAh, g_Ah);
    cudaGetSymbolAddress((void**)&pD, g_dinv);
    cudaGetSymbolAddress((void**)&pDeg, g_deg);
    cudaGetSymbolAddress((void**)&pOff, g_off);
    cudaGetSymbolAddress((void**)&pCur, g_cur);
    cudaGetSymbolAddress((void**)&pSrc, g_csrc);
    cudaGetSymbolAddress((void**)&pNrm, g_cnrm);

    cudaFuncSetAttribute((const void*)gemm_tc<false, false, false>,
                         cudaFuncAttributeMaxDynamicSharedMemorySize, TC_SMEM);
    cudaFuncSetAttribute((const void*)gemm_tc<true, false, false>,
                         cudaFuncAttributeMaxDynamicSharedMemorySize, TC_SMEM);
    cudaFuncSetAttribute((const void*)gemm_tc<true, true, true>,
                         cudaFuncAttributeMaxDynamicSharedMemorySize, TC_SMEM);

    int gb  = (n + 63) / 64;               // gemm blocks (64-row tiles)
    int nwb = (n + 7) / 8;                 // warp-per-node blocks
    int eb  = (int)((E + 255) / 256);      // thread-per-edge blocks

    // Launch order keeps the conv1 GEMM at index 3 so ncu (-s 5 -c 1) profiles it.
    detect_k<<<1, 256>>>((const int*)ei);                                  // 0
    zeroi_k<<<(100352 / 4 + 255) / 256, 256>>>((int4*)pDeg, 100352 / 4);   // 1
    deg_k<<<eb, 256>>>(ei, E, pDeg);                                       // 2
    gemm_tc<false, false, false><<<gb, 256, TC_SMEM>>>(x, nullptr, W1, nullptr, pXh, n); // 3
    dinv_k<<<(n + 255) / 256, 256>>>(pDeg, pD, n);                         // 4
    scan_k<<<1, 1024>>>(pDeg, pOff, pCur, n);                              // 5
    fill_k<<<eb, 256>>>(ei, E, pD, pCur, pSrc, pNrm);                      // 6

    // conv1 aggregate: Ah = tanh(gather(Xh) + self + b1)
    aggregate_k<<<nwb, 256>>>(pXh, pOff, pDeg, pSrc, pNrm, pD, b1, pAh, n);

    // conv2: Xh = Ah @ W2; Ah = tanh(gather(Xh) + self + b2)
    gemm_tc<true, false, false><<<gb, 256, TC_SMEM>>>(nullptr, pAh, W2, nullptr, pXh, n);
    aggregate_k<<<nwb, 256>>>(pXh, pOff, pDeg, pSrc, pNrm, pD, b2, pAh, n);

    // MLP head: all fp16 activations
    gemm_tc<true, true, true><<<gb, 256, TC_SMEM>>>(nullptr, pAh, lw1, lb1, pXh, n);
    gemm_tc<true, true, true><<<gb, 256, TC_SMEM>>>(nullptr, pXh, lw2, lb2, pAh, n);
    gemm_tc<true, true, true><<<gb, 256, TC_SMEM>>>(nullptr, pAh, lw3, lb3, pXh, n);
    out_k<<<(n + 7) / 8, 256>>>(pXh, lw4, lb4, out, n);
}